// round 10
// baseline (speedup 1.0000x reference)
#include <cuda_runtime.h>
#include <cuda_fp16.h>

#define N_NODES 100000
#define N_EDGES 1600000
#define F_IN 32
#define HID 16

// Scratch (no allocations allowed in kernel_launch)
__device__ __align__(16) float   g_deg [N_NODES];
__device__ __align__(16) __half2 g_xt_h[N_NODES * HID / 2];  // x @ W1_l.T (fp16)
__device__ __align__(16) float   g_xr1 [N_NODES * HID];      // x @ W1_r.T (fp32)
__device__ __align__(16) float   g_sum1[N_NODES * HID];      // fp32 accumulators
__device__ __align__(16) __half2 g_h_h [N_NODES * HID / 2];  // relu(layer1) (fp16)
__device__ __align__(16) float   g_sumh[N_NODES * HID];      // fp32 accumulators

__device__ __forceinline__ void red_add_v4(float* addr, float4 v) {
    asm volatile("red.global.add.v4.f32 [%0], {%1,%2,%3,%4};"
                 :: "l"(addr), "f"(v.x), "f"(v.y), "f"(v.z), "f"(v.w)
                 : "memory");
}

// Gather 8 halves (16B) and RED them as 2x fp32 float4 into dst.
__device__ __forceinline__ void gather_red8(const __half2* src_row8, float* dst8) {
    uint4 raw = *reinterpret_cast<const uint4*>(src_row8);
    const __half2* hp = reinterpret_cast<const __half2*>(&raw);
    float2 f0 = __half22float2(hp[0]);
    float2 f1 = __half22float2(hp[1]);
    float2 f2 = __half22float2(hp[2]);
    float2 f3 = __half22float2(hp[3]);
    red_add_v4(dst8,     make_float4(f0.x, f0.y, f1.x, f1.y));
    red_add_v4(dst8 + 4, make_float4(f2.x, f2.y, f3.x, f3.y));
}

// ---------------------------------------------------------------------------
// 0) zero scratch
// ---------------------------------------------------------------------------
__global__ void k_zero() {
    int i = blockIdx.x * blockDim.x + threadIdx.x;
    float4 z = make_float4(0.f, 0.f, 0.f, 0.f);
    if (i < N_NODES * HID / 4) {
        reinterpret_cast<float4*>(g_sum1)[i] = z;
        reinterpret_cast<float4*>(g_sumh)[i] = z;
    }
    if (i < N_NODES / 4) {
        reinterpret_cast<float4*>(g_deg)[i] = z;
    }
}

// ---------------------------------------------------------------------------
// 1) k_pre: 2 threads/node; m=0: xt=x@W1l.T -> fp16, m=1: xr1=x@W1r.T -> fp32.
//    Weights in smem with 528-float pad (conflict-free 2-address broadcast),
//    LDS.128 weight reads.
// ---------------------------------------------------------------------------
__global__ void __launch_bounds__(256) k_pre(const float* __restrict__ x,
                                             const float* __restrict__ W1l,
                                             const float* __restrict__ W1r) {
    __shared__ float WS[2 * 528];      // [0..511]=W1l, [528..1039]=W1r
    for (int i = threadIdx.x; i < HID * F_IN; i += blockDim.x) {
        WS[i]       = W1l[i];
        WS[528 + i] = W1r[i];
    }
    __syncthreads();

    unsigned t = blockIdx.x * blockDim.x + threadIdx.x;
    unsigned n = t >> 1;
    unsigned m = t & 1;
    if (n >= N_NODES) return;

    float xr[F_IN];
    const float4* xp = reinterpret_cast<const float4*>(x + (size_t)n * F_IN);
#pragma unroll
    for (int g = 0; g < F_IN / 4; g++) {
        float4 v = __ldg(xp + g);
        xr[4*g+0] = v.x; xr[4*g+1] = v.y; xr[4*g+2] = v.z; xr[4*g+3] = v.w;
    }

    const float4* ws4 = reinterpret_cast<const float4*>(WS + m * 528);

    float ov[HID];
#pragma unroll
    for (int o = 0; o < HID; o++) {
        float acc = 0.0f;
#pragma unroll
        for (int kg = 0; kg < F_IN / 4; kg++) {
            float4 w = ws4[o * (F_IN / 4) + kg];
            acc += xr[4*kg+0] * w.x + xr[4*kg+1] * w.y
                 + xr[4*kg+2] * w.z + xr[4*kg+3] * w.w;
        }
        ov[o] = acc;
    }

    if (m == 0) {
        __half2 hv[8];
#pragma unroll
        for (int i = 0; i < 8; i++) hv[i] = __floats2half2_rn(ov[2*i], ov[2*i+1]);
        uint4* src = reinterpret_cast<uint4*>(hv);
        uint4* dst = reinterpret_cast<uint4*>(g_xt_h + (size_t)n * (HID / 2));
        dst[0] = src[0];
        dst[1] = src[1];
    } else {
        float4* dp = reinterpret_cast<float4*>(g_xr1 + (size_t)n * HID);
#pragma unroll
        for (int g = 0; g < HID / 4; g++) {
            dp[g] = make_float4(ov[4*g+0], ov[4*g+1], ov[4*g+2], ov[4*g+3]);
        }
    }
}

// ---------------------------------------------------------------------------
// 2) edge scatter layer 1: sum1[dst] += fp32(xt_h[src]); deg[dst] += 1
//    2 threads per edge; each gathers 16B fp16, issues 2x red.v4 fp32.
// ---------------------------------------------------------------------------
__global__ void k_scatter1(const int* __restrict__ ei) {
    unsigned t = blockIdx.x * blockDim.x + threadIdx.x;
    unsigned e = t >> 1;
    unsigned q = t & 1;
    if (e >= N_EDGES) return;
    int s = __ldg(ei + e);
    int d = __ldg(ei + N_EDGES + e);

    if (q == 0) atomicAdd(&g_deg[d], 1.0f);

    gather_red8(g_xt_h + (size_t)s * (HID / 2) + q * 4,
                g_sum1 + (size_t)d * HID + q * 8);
}

// ---------------------------------------------------------------------------
// 3) h = relu(sum1/max(deg,1) + b1 + xr1) -> fp16   (2 threads/node)
// ---------------------------------------------------------------------------
__global__ void k_node1(const float* __restrict__ b1) {
    unsigned t = blockIdx.x * blockDim.x + threadIdx.x;
    unsigned n = t >> 1;
    unsigned q = t & 1;
    if (n >= N_NODES) return;

    float inv = 1.0f / fmaxf(__ldg(&g_deg[n]), 1.0f);

    const float4* sp = reinterpret_cast<const float4*>(g_sum1 + (size_t)n * HID + q * 8);
    const float4* rp = reinterpret_cast<const float4*>(g_xr1  + (size_t)n * HID + q * 8);
    const float4* bp = reinterpret_cast<const float4*>(b1) + q * 2;

    __half2 hv[4];
#pragma unroll
    for (int g = 0; g < 2; g++) {
        float4 s = sp[g];
        float4 r = rp[g];
        float4 b = __ldg(bp + g);
        float o0 = fmaxf(s.x * inv + b.x + r.x, 0.0f);
        float o1 = fmaxf(s.y * inv + b.y + r.y, 0.0f);
        float o2 = fmaxf(s.z * inv + b.z + r.z, 0.0f);
        float o3 = fmaxf(s.w * inv + b.w + r.w, 0.0f);
        hv[2*g+0] = __floats2half2_rn(o0, o1);
        hv[2*g+1] = __floats2half2_rn(o2, o3);
    }
    *reinterpret_cast<uint4*>(g_h_h + (size_t)n * (HID / 2) + q * 4) =
        *reinterpret_cast<uint4*>(hv);
}

// ---------------------------------------------------------------------------
// 4) edge scatter layer 2: sumh[dst] += fp32(h_h[src])  (2 threads/edge)
// ---------------------------------------------------------------------------
__global__ void k_scatter2(const int* __restrict__ ei) {
    unsigned t = blockIdx.x * blockDim.x + threadIdx.x;
    unsigned e = t >> 1;
    unsigned q = t & 1;
    if (e >= N_EDGES) return;
    int s = __ldg(ei + e);
    int d = __ldg(ei + N_EDGES + e);

    gather_red8(g_h_h  + (size_t)s * (HID / 2) + q * 4,
                g_sumh + (size_t)d * HID + q * 8);
}

// ---------------------------------------------------------------------------
// 5) k_node2: 1 thread/node, LDS.128 weight broadcasts.
//    out = (sumh*inv)@W2_l.T + b2 + h@W2_r.T   (h read as fp16)
// ---------------------------------------------------------------------------
__global__ void __launch_bounds__(256) k_node2(float* __restrict__ out,
                        const float* __restrict__ W2l,
                        const float* __restrict__ b2,
                        const float* __restrict__ W2r) {
    __shared__ float Wl[F_IN * HID];
    __shared__ float Wr[F_IN * HID];
    __shared__ float bs[F_IN];
    for (int i = threadIdx.x; i < F_IN * HID; i += blockDim.x) {
        Wl[i] = W2l[i];
        Wr[i] = W2r[i];
    }
    if (threadIdx.x < F_IN) bs[threadIdx.x] = b2[threadIdx.x];
    __syncthreads();

    int n = blockIdx.x * blockDim.x + threadIdx.x;
    if (n >= N_NODES) return;

    float inv = 1.0f / fmaxf(g_deg[n], 1.0f);

    float hr[HID], ar[HID];
    {
        const uint4* hp = reinterpret_cast<const uint4*>(g_h_h + (size_t)n * (HID / 2));
#pragma unroll
        for (int g = 0; g < 2; g++) {
            uint4 raw = hp[g];
            const __half2* h2 = reinterpret_cast<const __half2*>(&raw);
#pragma unroll
            for (int i = 0; i < 4; i++) {
                float2 f = __half22float2(h2[i]);
                hr[g*8 + 2*i + 0] = f.x;
                hr[g*8 + 2*i + 1] = f.y;
            }
        }
        const float4* ap = reinterpret_cast<const float4*>(g_sumh + (size_t)n * HID);
#pragma unroll
        for (int g = 0; g < HID / 4; g++) {
            float4 a = ap[g];
            ar[4*g+0] = a.x * inv; ar[4*g+1] = a.y * inv;
            ar[4*g+2] = a.z * inv; ar[4*g+3] = a.w * inv;
        }
    }

    const float4* Wl4 = reinterpret_cast<const float4*>(Wl);
    const float4* Wr4 = reinterpret_cast<const float4*>(Wr);

    float4* op = reinterpret_cast<float4*>(out + (size_t)n * F_IN);
#pragma unroll
    for (int fg = 0; fg < F_IN / 4; fg++) {
        float4 r;
        float* rp = &r.x;
#pragma unroll
        for (int ff = 0; ff < 4; ff++) {
            int f = fg * 4 + ff;
            float acc = bs[f];
#pragma unroll
            for (int kg = 0; kg < HID / 4; kg++) {
                float4 wl = Wl4[f * (HID / 4) + kg];
                float4 wr = Wr4[f * (HID / 4) + kg];
                acc += ar[4*kg+0] * wl.x + ar[4*kg+1] * wl.y
                     + ar[4*kg+2] * wl.z + ar[4*kg+3] * wl.w
                     + hr[4*kg+0] * wr.x + hr[4*kg+1] * wr.y
                     + hr[4*kg+2] * wr.z + hr[4*kg+3] * wr.w;
            }
            rp[ff] = acc;
        }
        op[fg] = r;
    }
}

// ---------------------------------------------------------------------------
extern "C" void kernel_launch(void* const* d_in, const int* in_sizes, int n_in,
                              void* d_out, int out_size) {
    const float* x   = (const float*)d_in[0];
    const int*   ei  = (const int*)d_in[1];   // [1,2,E], int32 (JAX x64 off)
    const float* W1l = (const float*)d_in[2];
    const float* b1  = (const float*)d_in[3];
    const float* W1r = (const float*)d_in[4];
    const float* W2l = (const float*)d_in[5];
    const float* b2  = (const float*)d_in[6];
    const float* W2r = (const float*)d_in[7];
    float*       out = (float*)d_out;

    const int T = 256;
    const int grid_zero  = (N_NODES * HID / 4 + T - 1) / T;
    const int grid_node  = (N_NODES + T - 1) / T;
    const int grid_node2 = (N_NODES * 2 + T - 1) / T;
    const int grid_edge2 = ((N_EDGES * 2) + T - 1) / T;

    k_zero    <<<grid_zero,  T>>>();
    k_pre     <<<grid_node2, T>>>(x, W1l, W1r);
    k_scatter1<<<grid_edge2, T>>>(ei);
    k_node1   <<<grid_node2, T>>>(b1);
    k_scatter2<<<grid_edge2, T>>>(ei);
    k_node2   <<<grid_node,  T>>>(out, W2l, b2, W2r);
}